// round 2
// baseline (speedup 1.0000x reference)
#include <cuda_runtime.h>
#include <math.h>

#define C_DIM 512
#define H_DIM 192
#define W_DIM 192
#define A_DIM 4608          // C*9
#define L_DIM 4096          // (192/3)^2
#define PHW   64            // 192/3
#define NTILE 36            // A_DIM / 128

// ---- scratch (static device allocations; no cudaMalloc anywhere) ----
__device__ float g_img[A_DIM * L_DIM];     // unfolded model_resp  (A, L) row-major
__device__ float g_sty[A_DIM * L_DIM];     // unfolded style_resp  (A, L) row-major
__device__ float g_invImg[A_DIM];
__device__ float g_invSty[A_DIM];
__device__ float g_pmax[NTILE * A_DIM];    // per-row-tile column max
__device__ int   g_pidx[NTILE * A_DIM];    // per-row-tile column argmax

// ---------------------------------------------------------------------------
// 1) Unfold: out[a, l] = in[c, 3*ph+kh, 3*pw+kw],  a=c*9+kh*3+kw, l=ph*64+pw
//    Output-indexed => coalesced writes.
// ---------------------------------------------------------------------------
__global__ void unfold_kernel(const float* __restrict__ in, int which) {
    float* __restrict__ out = which ? g_sty : g_img;
    int idx = blockIdx.x * blockDim.x + threadIdx.x;
    if (idx >= A_DIM * L_DIM) return;
    int a  = idx / L_DIM;
    int l  = idx - a * L_DIM;
    int c  = a / 9;
    int r  = a - c * 9;
    int kh = r / 3;
    int kw = r - kh * 3;
    int ph = l / PHW;
    int pw = l - ph * PHW;
    int h = ph * 3 + kh;
    int w = pw * 3 + kw;
    out[idx] = in[(c * H_DIM + h) * W_DIM + w];
}

// ---------------------------------------------------------------------------
// 2) Row inverse norms: 1/||row||_2 for both matrices (block per row)
// ---------------------------------------------------------------------------
__global__ void norm_kernel() {
    const int row = blockIdx.x;                 // 0 .. 2*A_DIM-1
    const float* base = (row < A_DIM) ? &g_img[row * L_DIM]
                                      : &g_sty[(row - A_DIM) * L_DIM];
    float s = 0.0f;
    for (int i = threadIdx.x; i < L_DIM; i += 256) {
        float v = base[i];
        s = fmaf(v, v, s);
    }
    __shared__ float sh[8];
    #pragma unroll
    for (int o = 16; o > 0; o >>= 1) s += __shfl_down_sync(0xffffffffu, s, o);
    if ((threadIdx.x & 31) == 0) sh[threadIdx.x >> 5] = s;
    __syncthreads();
    if (threadIdx.x < 32) {
        s = (threadIdx.x < 8) ? sh[threadIdx.x] : 0.0f;
        #pragma unroll
        for (int o = 4; o > 0; o >>= 1) s += __shfl_down_sync(0xffffffffu, s, o);
        if (threadIdx.x == 0) {
            float inv = 1.0f / sqrtf(s);
            if (row < A_DIM) g_invImg[row] = inv;
            else             g_invSty[row - A_DIM] = inv;
        }
    }
}

// ---------------------------------------------------------------------------
// 3) GEMM D[i,j] = sty_i . img_j with fused column-wise max of D[i,j]*invImg[i]
//    128x128 tile, BK=16, 256 threads, 8x8 per thread, double-buffered smem.
//    Block (bm,bn) -> rows [bm*128,..), cols [bn*128,..). Writes one partial
//    (max, argmax) per column into g_pmax/g_pidx[bm][col].
// ---------------------------------------------------------------------------
struct SmemGemm { float As[2][16][132]; float Bs[2][16][132]; };
struct SmemRed  { float v[16][128]; int i[16][128]; };

__global__ __launch_bounds__(256, 2)
void gemm_colmax_kernel() {
    __shared__ union { SmemGemm g; SmemRed r; } sm;

    const int bm = blockIdx.y, bn = blockIdx.x;
    const int m0 = bm * 128, n0 = bn * 128;
    const int tid = threadIdx.x;
    const int tx = tid & 15, ty = tid >> 4;

    // global load mapping: 256 threads, each loads 2 float4 per matrix per tile
    const int lr = tid >> 2;            // 0..63
    const int lc = (tid & 3) << 2;      // 0,4,8,12
    const float* pA = g_sty + (m0 + lr) * L_DIM + lc;
    const float* pB = g_img + (n0 + lr) * L_DIM + lc;
    const int rowOff = 64 * L_DIM;

    // prologue: load k-tile 0
    float4 ra0 = *(const float4*)(pA);
    float4 ra1 = *(const float4*)(pA + rowOff);
    float4 rb0 = *(const float4*)(pB);
    float4 rb1 = *(const float4*)(pB + rowOff);

    sm.g.As[0][lc+0][lr]    = ra0.x; sm.g.As[0][lc+1][lr]    = ra0.y;
    sm.g.As[0][lc+2][lr]    = ra0.z; sm.g.As[0][lc+3][lr]    = ra0.w;
    sm.g.As[0][lc+0][lr+64] = ra1.x; sm.g.As[0][lc+1][lr+64] = ra1.y;
    sm.g.As[0][lc+2][lr+64] = ra1.z; sm.g.As[0][lc+3][lr+64] = ra1.w;
    sm.g.Bs[0][lc+0][lr]    = rb0.x; sm.g.Bs[0][lc+1][lr]    = rb0.y;
    sm.g.Bs[0][lc+2][lr]    = rb0.z; sm.g.Bs[0][lc+3][lr]    = rb0.w;
    sm.g.Bs[0][lc+0][lr+64] = rb1.x; sm.g.Bs[0][lc+1][lr+64] = rb1.y;
    sm.g.Bs[0][lc+2][lr+64] = rb1.z; sm.g.Bs[0][lc+3][lr+64] = rb1.w;
    __syncthreads();

    float acc[8][8];
    #pragma unroll
    for (int i = 0; i < 8; ++i)
        #pragma unroll
        for (int j = 0; j < 8; ++j) acc[i][j] = 0.0f;

    const int NT = L_DIM / 16;   // 256
    for (int t = 0; t < NT; ++t) {
        const int cur = t & 1;
        if (t + 1 < NT) {
            const float* qA = pA + (t + 1) * 16;
            const float* qB = pB + (t + 1) * 16;
            ra0 = *(const float4*)(qA);
            ra1 = *(const float4*)(qA + rowOff);
            rb0 = *(const float4*)(qB);
            rb1 = *(const float4*)(qB + rowOff);
        }
        #pragma unroll
        for (int k = 0; k < 16; ++k) {
            float a[8], b[8];
            *(float4*)&a[0] = *(const float4*)&sm.g.As[cur][k][ty * 4];
            *(float4*)&a[4] = *(const float4*)&sm.g.As[cur][k][64 + ty * 4];
            *(float4*)&b[0] = *(const float4*)&sm.g.Bs[cur][k][tx * 4];
            *(float4*)&b[4] = *(const float4*)&sm.g.Bs[cur][k][64 + tx * 4];
            #pragma unroll
            for (int i = 0; i < 8; ++i)
                #pragma unroll
                for (int j = 0; j < 8; ++j)
                    acc[i][j] = fmaf(a[i], b[j], acc[i][j]);
        }
        if (t + 1 < NT) {
            const int nxt = cur ^ 1;
            sm.g.As[nxt][lc+0][lr]    = ra0.x; sm.g.As[nxt][lc+1][lr]    = ra0.y;
            sm.g.As[nxt][lc+2][lr]    = ra0.z; sm.g.As[nxt][lc+3][lr]    = ra0.w;
            sm.g.As[nxt][lc+0][lr+64] = ra1.x; sm.g.As[nxt][lc+1][lr+64] = ra1.y;
            sm.g.As[nxt][lc+2][lr+64] = ra1.z; sm.g.As[nxt][lc+3][lr+64] = ra1.w;
            sm.g.Bs[nxt][lc+0][lr]    = rb0.x; sm.g.Bs[nxt][lc+1][lr]    = rb0.y;
            sm.g.Bs[nxt][lc+2][lr]    = rb0.z; sm.g.Bs[nxt][lc+3][lr]    = rb0.w;
            sm.g.Bs[nxt][lc+0][lr+64] = rb1.x; sm.g.Bs[nxt][lc+1][lr+64] = rb1.y;
            sm.g.Bs[nxt][lc+2][lr+64] = rb1.z; sm.g.Bs[nxt][lc+3][lr+64] = rb1.w;
        }
        __syncthreads();
    }

    // ---- fused epilogue: per-column max of acc[i][j] * invImg[row_i] ----
    float inv[8];
    #pragma unroll
    for (int u = 0; u < 8; ++u) {
        int row = (u < 4) ? (ty * 4 + u) : (64 + ty * 4 + (u - 4));
        inv[u] = g_invImg[m0 + row];
    }
    // (smem union reuse: safe — loop ended with __syncthreads)
    #pragma unroll
    for (int q = 0; q < 8; ++q) {
        int colLocal = (q < 4) ? (tx * 4 + q) : (64 + tx * 4 + (q - 4));
        float bv = -3.402823466e38f;
        int   bi = 0x7fffffff;
        #pragma unroll
        for (int u = 0; u < 8; ++u) {
            int row = (u < 4) ? (ty * 4 + u) : (64 + ty * 4 + (u - 4));
            float v = acc[u][q] * inv[u];
            int gi = m0 + row;
            if (v > bv || (v == bv && gi < bi)) { bv = v; bi = gi; }
        }
        sm.r.v[ty][colLocal] = bv;
        sm.r.i[ty][colLocal] = bi;
    }
    __syncthreads();
    if (tid < 128) {
        float bv = sm.r.v[0][tid];
        int   bi = sm.r.i[0][tid];
        #pragma unroll
        for (int t2 = 1; t2 < 16; ++t2) {
            float v = sm.r.v[t2][tid];
            int  i2 = sm.r.i[t2][tid];
            if (v > bv || (v == bv && i2 < bi)) { bv = v; bi = i2; }
        }
        g_pmax[bm * A_DIM + n0 + tid] = bv;
        g_pidx[bm * A_DIM + n0 + tid] = bi;
    }
}

// ---------------------------------------------------------------------------
// 4) Final reduce over 36 row-tile partials per column; output
//    out[0..A) = nearest (as float), out[A..2A) = max_sim
// ---------------------------------------------------------------------------
__global__ void final_kernel(float* __restrict__ out) {
    int j = blockIdx.x * blockDim.x + threadIdx.x;
    if (j >= A_DIM) return;
    float bv = g_pmax[j];
    int   bi = g_pidx[j];
    #pragma unroll 4
    for (int t = 1; t < NTILE; ++t) {
        float v = g_pmax[t * A_DIM + j];
        int   i = g_pidx[t * A_DIM + j];
        if (v > bv || (v == bv && i < bi)) { bv = v; bi = i; }
    }
    out[j]         = (float)bi;
    out[A_DIM + j] = bv * g_invSty[j];
}

// ---------------------------------------------------------------------------
extern "C" void kernel_launch(void* const* d_in, const int* in_sizes, int n_in,
                              void* d_out, int out_size) {
    const float* model = (const float*)d_in[0];
    const float* style = (const float*)d_in[1];
    float* out = (float*)d_out;

    const int totalUF = A_DIM * L_DIM;
    unfold_kernel<<<(totalUF + 255) / 256, 256>>>(model, 0);
    unfold_kernel<<<(totalUF + 255) / 256, 256>>>(style, 1);
    norm_kernel<<<2 * A_DIM, 256>>>();
    gemm_colmax_kernel<<<dim3(NTILE, NTILE), 256>>>();
    final_kernel<<<A_DIM / 256, 256>>>(out);
}

// round 4
// speedup vs baseline: 2.0742x; 2.0742x over previous
#include <cuda_runtime.h>
#include <cuda_bf16.h>
#include <math.h>
#include <stdint.h>

#define A_DIM 4608
#define L_DIM 4096
#define H_DIM 192
#define W_DIM 192
#define PHW   64
#define NTILE 36          // A_DIM / 128
#define BK    32
#define NIT   (3 * (L_DIM / BK))   // 384
#define PITCHB 80         // smem row pitch bytes (32 bf16 = 64B + 16B pad)
#define STAGE  (128 * PITCHB * 2)  // A tile + B tile = 20480 B
#define NSTG   3
#define EPI_PITCH 132
#define SMEM_BYTES (128 * EPI_PITCH * 4)   // 67584 >= 3*STAGE (61440)

__device__ __nv_bfloat16 g_imgHi[(size_t)A_DIM * L_DIM];
__device__ __nv_bfloat16 g_imgLo[(size_t)A_DIM * L_DIM];
__device__ __nv_bfloat16 g_styHi[(size_t)A_DIM * L_DIM];
__device__ __nv_bfloat16 g_styLo[(size_t)A_DIM * L_DIM];
__device__ float g_invImg[A_DIM];
__device__ float g_invSty[A_DIM];
__device__ float g_pmax[NTILE * A_DIM];
__device__ int   g_pidx[NTILE * A_DIM];

__device__ __forceinline__ uint32_t smem_u32(const void* p) {
    uint32_t a;
    asm("{ .reg .u64 t; cvta.to.shared.u64 t, %1; cvt.u32.u64 %0, t; }" : "=r"(a) : "l"(p));
    return a;
}
#define CP16(dst, src) \
    asm volatile("cp.async.cg.shared.global [%0], [%1], 16;" :: "r"(dst), "l"(src) : "memory")
#define CP_COMMIT() asm volatile("cp.async.commit_group;" ::: "memory")
#define CP_WAIT1()  asm volatile("cp.async.wait_group 1;" ::: "memory")
#define CP_WAIT0()  asm volatile("cp.async.wait_group 0;" ::: "memory")
#define LDSM4(r0, r1, r2, r3, a) \
    asm volatile("ldmatrix.sync.aligned.m8n8.x4.shared.b16 {%0,%1,%2,%3}, [%4];" \
        : "=r"(r0), "=r"(r1), "=r"(r2), "=r"(r3) : "r"(a))
#define MMA_BF16(c, a, b) \
    asm volatile("mma.sync.aligned.m16n8k16.row.col.f32.bf16.bf16.f32 " \
        "{%0,%1,%2,%3}, {%4,%5,%6,%7}, {%8,%9}, {%0,%1,%2,%3};" \
        : "+f"((c)[0]), "+f"((c)[1]), "+f"((c)[2]), "+f"((c)[3]) \
        : "r"((a)[0]), "r"((a)[1]), "r"((a)[2]), "r"((a)[3]), "r"((b)[0]), "r"((b)[1]))

// ---------------------------------------------------------------------------
// 1) unfold + bf16 hi/lo split
// ---------------------------------------------------------------------------
__global__ void unfold_split(const float* __restrict__ in, int which) {
    int idx = blockIdx.x * blockDim.x + threadIdx.x;
    if (idx >= A_DIM * L_DIM) return;
    int a = idx / L_DIM, l = idx - a * L_DIM;
    int c = a / 9, r = a - c * 9;
    int kh = r / 3, kw = r - kh * 3;
    int ph = l / PHW, pw = l - ph * PHW;
    float v = in[(c * H_DIM + ph * 3 + kh) * W_DIM + pw * 3 + kw];
    __nv_bfloat16 hi = __float2bfloat16(v);
    __nv_bfloat16 lo = __float2bfloat16(v - __bfloat162float(hi));
    if (which) { g_styHi[idx] = hi; g_styLo[idx] = lo; }
    else       { g_imgHi[idx] = hi; g_imgLo[idx] = lo; }
}

// ---------------------------------------------------------------------------
// 2) row inverse norms (hi+lo reconstruction; rel err ~1e-5)
// ---------------------------------------------------------------------------
__global__ void norm_kernel() {
    const int row = blockIdx.x;
    const __nv_bfloat16* hi = (row < A_DIM) ? &g_imgHi[(size_t)row * L_DIM]
                                            : &g_styHi[(size_t)(row - A_DIM) * L_DIM];
    const __nv_bfloat16* lo = (row < A_DIM) ? &g_imgLo[(size_t)row * L_DIM]
                                            : &g_styLo[(size_t)(row - A_DIM) * L_DIM];
    float s = 0.0f;
    for (int i = threadIdx.x; i < L_DIM; i += 256) {
        float v = __bfloat162float(hi[i]) + __bfloat162float(lo[i]);
        s = fmaf(v, v, s);
    }
    __shared__ float sh[8];
    #pragma unroll
    for (int o = 16; o > 0; o >>= 1) s += __shfl_down_sync(0xffffffffu, s, o);
    if ((threadIdx.x & 31) == 0) sh[threadIdx.x >> 5] = s;
    __syncthreads();
    if (threadIdx.x < 32) {
        s = (threadIdx.x < 8) ? sh[threadIdx.x] : 0.0f;
        #pragma unroll
        for (int o = 4; o > 0; o >>= 1) s += __shfl_down_sync(0xffffffffu, s, o);
        if (threadIdx.x == 0) {
            float inv = 1.0f / sqrtf(s);
            if (row < A_DIM) g_invImg[row] = inv;
            else             g_invSty[row - A_DIM] = inv;
        }
    }
}

// ---------------------------------------------------------------------------
// 3) bf16x3 mma.sync GEMM (128x128 tile) + fused column max/argmax
//    D[i,j] = sty_i . img_j over 3 passes: (hi,hi), (hi,lo), (lo,hi)
// ---------------------------------------------------------------------------
__global__ void __launch_bounds__(256)
gemm_mma() {
    extern __shared__ char smem[];
    const uint32_t sb = smem_u32(smem);
    const int tid = threadIdx.x;
    const int wid = tid >> 5, lane = tid & 31;
    const int warp_m = wid & 3, warp_n = wid >> 2;     // 4 x 2 warps
    const int m_base = warp_m * 32, n_base = warp_n * 64;
    const int bm = blockIdx.x, bn = blockIdx.y;
    const int m0 = bm * 128, n0 = bn * 128;

    // per-pass global bases (A = sty rows m0.., B = img rows n0..)
    const __nv_bfloat16* passA[3] = {
        g_styHi + (size_t)m0 * L_DIM, g_styHi + (size_t)m0 * L_DIM, g_styLo + (size_t)m0 * L_DIM };
    const __nv_bfloat16* passB[3] = {
        g_imgHi + (size_t)n0 * L_DIM, g_imgLo + (size_t)n0 * L_DIM, g_imgHi + (size_t)n0 * L_DIM };

    // cp.async mapping: 512 16B-chunks per matrix; thread does chunks tid, tid+256
    const int r0c = tid >> 2, c0c = tid & 3;           // chunk tid
    const int r1c = (tid + 256) >> 2, c1c = tid & 3;   // chunk tid+256

    // issue one k-tile into stage s for global iteration 'it'
    auto issue = [&](int it, int s) {
        const int p = it >> 7;                  // pass 0..2
        const int kx = (it & 127) * BK;         // k offset (elements)
        const __nv_bfloat16* gA = passA[p] + kx;
        const __nv_bfloat16* gB = passB[p] + kx;
        uint32_t stA = sb + s * STAGE;
        uint32_t stB = stA + 128 * PITCHB;
        CP16(stA + r0c * PITCHB + c0c * 16, gA + (size_t)r0c * L_DIM + c0c * 8);
        CP16(stA + r1c * PITCHB + c1c * 16, gA + (size_t)r1c * L_DIM + c1c * 8);
        CP16(stB + r0c * PITCHB + c0c * 16, gB + (size_t)r0c * L_DIM + c0c * 8);
        CP16(stB + r1c * PITCHB + c1c * 16, gB + (size_t)r1c * L_DIM + c1c * 8);
        CP_COMMIT();
    };

    float acc[2][8][4];
    #pragma unroll
    for (int i = 0; i < 2; ++i)
        #pragma unroll
        for (int j = 0; j < 8; ++j)
            #pragma unroll
            for (int k = 0; k < 4; ++k) acc[i][j][k] = 0.0f;

    issue(0, 0);
    issue(1, 1);

    // precomputed ldmatrix lane addresses (offsets within stage)
    const uint32_t aOff = (uint32_t)(m_base + (lane & 15)) * PITCHB + (lane >> 4) * 16;
    const uint32_t bRow = (uint32_t)(n_base + ((lane >> 4) * 8) + (lane & 7)) * PITCHB
                        + (((lane >> 3) & 1) * 16);

    for (int it = 0; it < NIT; ++it) {
        const int s = it % NSTG;
        if (it + 2 < NIT) { CP_WAIT1(); } else { CP_WAIT0(); }
        __syncthreads();
        if (it + 2 < NIT) issue(it + 2, (it + 2) % NSTG);

        const uint32_t stA = sb + s * STAGE;
        const uint32_t stB = stA + 128 * PITCHB;
        #pragma unroll
        for (int ks = 0; ks < 2; ++ks) {
            uint32_t a0[2][4];
            #pragma unroll
            for (int mt = 0; mt < 2; ++mt)
                LDSM4(a0[mt][0], a0[mt][1], a0[mt][2], a0[mt][3],
                      stA + aOff + mt * 16 * PITCHB + ks * 32);
            uint32_t b0[4][4];
            #pragma unroll
            for (int np = 0; np < 4; ++np)
                LDSM4(b0[np][0], b0[np][1], b0[np][2], b0[np][3],
                      stB + bRow + np * 16 * PITCHB + ks * 32);
            #pragma unroll
            for (int mt = 0; mt < 2; ++mt)
                #pragma unroll
                for (int np = 0; np < 4; ++np) {
                    MMA_BF16(acc[mt][np * 2],     a0[mt], (&b0[np][0]));
                    MMA_BF16(acc[mt][np * 2 + 1], a0[mt], (&b0[np][2]));
                }
        }
        __syncthreads();
    }

    // ---- fused epilogue: scaled tile -> smem -> column max/argmax ----
    float* epi = (float*)smem;     // [128][132]
    float invR[4];
    #pragma unroll
    for (int mt = 0; mt < 2; ++mt)
        #pragma unroll
        for (int h = 0; h < 2; ++h)
            invR[mt * 2 + h] = g_invImg[m0 + m_base + mt * 16 + h * 8 + (lane >> 2)];

    #pragma unroll
    for (int mt = 0; mt < 2; ++mt)
        #pragma unroll
        for (int np = 0; np < 8; ++np)
            #pragma unroll
            for (int h = 0; h < 2; ++h) {
                int row = m_base + mt * 16 + h * 8 + (lane >> 2);
                int col = n_base + np * 8 + (lane & 3) * 2;
                epi[row * EPI_PITCH + col]     = acc[mt][np][h * 2]     * invR[mt * 2 + h];
                epi[row * EPI_PITCH + col + 1] = acc[mt][np][h * 2 + 1] * invR[mt * 2 + h];
            }
    __syncthreads();

    if (tid < 128) {
        float bv = -3.402823466e38f;
        int bi = 0;
        #pragma unroll 8
        for (int r = 0; r < 128; ++r) {          // ascending rows: > keeps first
            float v = epi[r * EPI_PITCH + tid];
            if (v > bv) { bv = v; bi = m0 + r; }
        }
        g_pmax[bm * A_DIM + n0 + tid] = bv;
        g_pidx[bm * A_DIM + n0 + tid] = bi;
    }
}

// ---------------------------------------------------------------------------
// 4) final reduce over 36 row-tile partials
// ---------------------------------------------------------------------------
__global__ void final_kernel(float* __restrict__ out) {
    int j = blockIdx.x * blockDim.x + threadIdx.x;
    if (j >= A_DIM) return;
    float bv = g_pmax[j];
    int bi = g_pidx[j];
    #pragma unroll 4
    for (int t = 1; t < NTILE; ++t) {
        float v = g_pmax[t * A_DIM + j];
        int i = g_pidx[t * A_DIM + j];
        if (v > bv || (v == bv && i < bi)) { bv = v; bi = i; }
    }
    out[j]         = (float)bi;
    out[A_DIM + j] = bv * g_invSty[j];
}

// ---------------------------------------------------------------------------
extern "C" void kernel_launch(void* const* d_in, const int* in_sizes, int n_in,
                              void* d_out, int out_size) {
    const float* model = (const float*)d_in[0];
    const float* style = (const float*)d_in[1];
    float* out = (float*)d_out;

    cudaFuncSetAttribute(gemm_mma, cudaFuncAttributeMaxDynamicSharedMemorySize, SMEM_BYTES);

    const int tot = A_DIM * L_DIM;
    unfold_split<<<(tot + 255) / 256, 256>>>(model, 0);
    unfold_split<<<(tot + 255) / 256, 256>>>(style, 1);
    norm_kernel<<<2 * A_DIM, 256>>>();
    gemm_mma<<<dim3(NTILE, NTILE), 256, SMEM_BYTES>>>();
    final_kernel<<<A_DIM / 256, 256>>>(out);
}